// round 1
// baseline (speedup 1.0000x reference)
#include <cuda_runtime.h>
#include <math.h>

#define B_  2
#define S_  2048
#define E_  1024
#define H_  16
#define DH_ 64

// Scratch (allocation-free rule: __device__ globals)
__device__ float g_q[(size_t)B_ * H_ * S_ * DH_];   // [B,H,S,DH]
__device__ float g_k[(size_t)B_ * H_ * S_ * DH_];
__device__ float g_v[(size_t)B_ * H_ * S_ * DH_];
__device__ float g_ao[(size_t)B_ * S_ * E_];        // attention out, [B,S,H*DH]

// ---------------------------------------------------------------------------
// Tiled SGEMM: C[m0:m0+64, n0:n0+64] = A[m0:,:K] @ B[:K, n0:] + bias[n0:]
// A row-major (lda), B row-major (ldb), C row-major (ldc). 256 threads.
// ---------------------------------------------------------------------------
__device__ __forceinline__ void gemm64_tile(
    const float* __restrict__ A, int lda,
    const float* __restrict__ Bm, int ldb,
    const float* __restrict__ bias,
    float* __restrict__ C, int ldc,
    int K, int m0, int n0)
{
    __shared__ float As[64][20];   // [m][k], padded row stride 20 (16B-aligned rows)
    __shared__ float Bs[16][64];   // [k][n]

    const int tid = threadIdx.x;
    const int tx = tid & 15;       // 0..15 -> N
    const int ty = tid >> 4;       // 0..15 -> M

    const int arow = tid >> 2;           // 0..63
    const int acol = (tid & 3) * 4;      // 0,4,8,12
    const int brow = tid >> 4;           // 0..15
    const int bcol = (tid & 15) * 4;     // 0..60

    float acc[4][4] = {{0.f, 0.f, 0.f, 0.f}, {0.f, 0.f, 0.f, 0.f},
                       {0.f, 0.f, 0.f, 0.f}, {0.f, 0.f, 0.f, 0.f}};

    for (int k0 = 0; k0 < K; k0 += 16) {
        float4 av = *(const float4*)(A + (size_t)(m0 + arow) * lda + k0 + acol);
        float4 bv = *(const float4*)(Bm + (size_t)(k0 + brow) * ldb + n0 + bcol);
        *(float4*)(&As[arow][acol]) = av;
        *(float4*)(&Bs[brow][bcol]) = bv;
        __syncthreads();

#pragma unroll
        for (int kk = 0; kk < 16; kk++) {
            float a0 = As[ty * 4 + 0][kk];
            float a1 = As[ty * 4 + 1][kk];
            float a2 = As[ty * 4 + 2][kk];
            float a3 = As[ty * 4 + 3][kk];
            float4 b = *(const float4*)(&Bs[kk][tx * 4]);
            acc[0][0] += a0 * b.x; acc[0][1] += a0 * b.y; acc[0][2] += a0 * b.z; acc[0][3] += a0 * b.w;
            acc[1][0] += a1 * b.x; acc[1][1] += a1 * b.y; acc[1][2] += a1 * b.z; acc[1][3] += a1 * b.w;
            acc[2][0] += a2 * b.x; acc[2][1] += a2 * b.y; acc[2][2] += a2 * b.z; acc[2][3] += a2 * b.w;
            acc[3][0] += a3 * b.x; acc[3][1] += a3 * b.y; acc[3][2] += a3 * b.z; acc[3][3] += a3 * b.w;
        }
        __syncthreads();
    }

#pragma unroll
    for (int i = 0; i < 4; i++) {
        float* crow = C + (size_t)(m0 + ty * 4 + i) * ldc + n0 + tx * 4;
        const float* brow_bias = bias + n0 + tx * 4;
        float4 o;
        o.x = acc[i][0] + brow_bias[0];
        o.y = acc[i][1] + brow_bias[1];
        o.z = acc[i][2] + brow_bias[2];
        o.w = acc[i][3] + brow_bias[3];
        *(float4*)crow = o;
    }
}

// ---------------------------------------------------------------------------
// QKV projection: q/k/v[b,h,s,d] = x[b,s,:] @ w*[h,:,d] + b*[h,d]
// grid: (S/64, B*H, 3), block 256
// ---------------------------------------------------------------------------
__global__ __launch_bounds__(256) void qkv_kernel(
    const float* __restrict__ x,
    const float* __restrict__ wq, const float* __restrict__ bq,
    const float* __restrict__ wk, const float* __restrict__ bk,
    const float* __restrict__ wv, const float* __restrict__ bv)
{
    const int which = blockIdx.z;
    const int bh = blockIdx.y;
    const int b = bh >> 4;
    const int h = bh & (H_ - 1);

    const float* W;
    const float* bias;
    float* C;
    if (which == 0)      { W = wq; bias = bq; C = g_q; }
    else if (which == 1) { W = wk; bias = bk; C = g_k; }
    else                 { W = wv; bias = bv; C = g_v; }

    gemm64_tile(x + (size_t)b * S_ * E_, E_,
                W + (size_t)h * E_ * DH_, DH_,
                bias + (size_t)h * DH_,
                C + (size_t)bh * S_ * DH_, DH_,
                E_, blockIdx.x * 64, 0);
}

// ---------------------------------------------------------------------------
// Output projection: out[4096,1024] = g_ao @ wo + bo
// grid: (B*S/64, E/64), block 256
// ---------------------------------------------------------------------------
__global__ __launch_bounds__(256) void proj_kernel(
    const float* __restrict__ wo, const float* __restrict__ bo,
    float* __restrict__ out)
{
    gemm64_tile(g_ao, E_, wo, E_, bo, out, E_, E_,
                blockIdx.x * 64, blockIdx.y * 64);
}

// ---------------------------------------------------------------------------
// Flash attention: 1 thread = 1 query row; 64-key tiles in shared.
// grid: (S/128, B*H), block 128
// ---------------------------------------------------------------------------
__global__ __launch_bounds__(128) void attn_kernel(const int* __restrict__ mask)
{
    __shared__ float Ks[64][64];
    __shared__ float Vs[64][64];
    __shared__ float mk[64];

    const int tid = threadIdx.x;
    const int bh = blockIdx.y;
    const int b = bh >> 4;
    const int h = bh & (H_ - 1);
    const int row = blockIdx.x * 128 + tid;

    const float* qp = g_q + ((size_t)bh * S_ + row) * DH_;
    const float* kbase = g_k + (size_t)bh * S_ * DH_;
    const float* vbase = g_v + (size_t)bh * S_ * DH_;

    float qr[64];
#pragma unroll
    for (int i = 0; i < 16; i++) {
        float4 t = *(const float4*)(qp + i * 4);
        qr[i * 4 + 0] = t.x; qr[i * 4 + 1] = t.y;
        qr[i * 4 + 2] = t.z; qr[i * 4 + 3] = t.w;
    }

    float acc[64];
#pragma unroll
    for (int d = 0; d < 64; d++) acc[d] = 0.f;
    float m = -1e30f, l = 0.f;

    const int jr = tid >> 1;            // row to load (0..63)
    const int dofs = (tid & 1) * 32;    // half of DH

    for (int kt = 0; kt < S_; kt += 64) {
        // stage K/V tiles
#pragma unroll
        for (int i = 0; i < 8; i++) {
            *(float4*)(&Ks[jr][dofs + i * 4]) =
                *(const float4*)(kbase + (size_t)(kt + jr) * DH_ + dofs + i * 4);
            *(float4*)(&Vs[jr][dofs + i * 4]) =
                *(const float4*)(vbase + (size_t)(kt + jr) * DH_ + dofs + i * 4);
        }
        if (tid < 64)
            mk[tid] = (mask[b * S_ + kt + tid] == 0) ? -1e9f : 0.f;
        __syncthreads();

#pragma unroll 1
        for (int j0 = 0; j0 < 64; j0 += 16) {
            float s[16];
#pragma unroll
            for (int jj = 0; jj < 16; jj++) {
                float d0 = 0.f;
#pragma unroll
                for (int d4 = 0; d4 < 16; d4++) {
                    float4 kv = *(const float4*)(&Ks[j0 + jj][d4 * 4]);
                    d0 += qr[d4 * 4 + 0] * kv.x + qr[d4 * 4 + 1] * kv.y +
                          qr[d4 * 4 + 2] * kv.z + qr[d4 * 4 + 3] * kv.w;
                }
                s[jj] = d0 * 0.125f + mk[j0 + jj];   // 1/sqrt(64) = 0.125
            }

            float tm = s[0];
#pragma unroll
            for (int jj = 1; jj < 16; jj++) tm = fmaxf(tm, s[jj]);
            float mn = fmaxf(m, tm);
            float corr = __expf(m - mn);
            m = mn;
            l *= corr;
#pragma unroll
            for (int d = 0; d < 64; d++) acc[d] *= corr;

#pragma unroll
            for (int jj = 0; jj < 16; jj++) {
                float p = __expf(s[jj] - mn);
                l += p;
#pragma unroll
                for (int d4 = 0; d4 < 16; d4++) {
                    float4 vv = *(const float4*)(&Vs[j0 + jj][d4 * 4]);
                    acc[d4 * 4 + 0] += p * vv.x;
                    acc[d4 * 4 + 1] += p * vv.y;
                    acc[d4 * 4 + 2] += p * vv.z;
                    acc[d4 * 4 + 3] += p * vv.w;
                }
            }
        }
        __syncthreads();
    }

    const float inv = 1.f / l;
    float* op = g_ao + ((size_t)b * S_ + row) * E_ + (size_t)h * DH_;
#pragma unroll
    for (int d4 = 0; d4 < 16; d4++) {
        float4 o;
        o.x = acc[d4 * 4 + 0] * inv;
        o.y = acc[d4 * 4 + 1] * inv;
        o.z = acc[d4 * 4 + 2] * inv;
        o.w = acc[d4 * 4 + 3] * inv;
        *(float4*)(op + d4 * 4) = o;
    }
}

// ---------------------------------------------------------------------------
extern "C" void kernel_launch(void* const* d_in, const int* in_sizes, int n_in,
                              void* d_out, int out_size)
{
    const float* x    = (const float*)d_in[0];
    const int*   mask = (const int*)  d_in[1];
    const float* wq   = (const float*)d_in[2];
    const float* bq   = (const float*)d_in[3];
    const float* wk   = (const float*)d_in[4];
    const float* bk   = (const float*)d_in[5];
    const float* wv   = (const float*)d_in[6];
    const float* bv   = (const float*)d_in[7];
    const float* wo   = (const float*)d_in[8];
    const float* bo   = (const float*)d_in[9];
    float* out = (float*)d_out;

    dim3 g1(S_ / 64, B_ * H_, 3);
    qkv_kernel<<<g1, 256>>>(x, wq, bq, wk, bk, wv, bv);

    dim3 g2(S_ / 128, B_ * H_);
    attn_kernel<<<g2, 128>>>(mask);

    dim3 g3((B_ * S_) / 64, E_ / 64);
    proj_kernel<<<g3, 256>>>(wo, bo, out);
}

// round 2
// speedup vs baseline: 3.2072x; 3.2072x over previous
#include <cuda_runtime.h>
#include <math.h>
#include <stdint.h>

#define B_  2
#define S_  2048
#define E_  1024
#define H_  16
#define DH_ 64

// Scratch (allocation-free rule: __device__ globals)
__device__ float g_q[(size_t)B_ * H_ * S_ * DH_];   // [B,H,S,DH]
__device__ float g_k[(size_t)B_ * H_ * S_ * DH_];
__device__ float g_v[(size_t)B_ * H_ * S_ * DH_];
__device__ float g_ao[(size_t)B_ * S_ * E_];        // attention out, [B,S,H*DH]

// ---------------------------------------------------------------------------
// tf32 helpers
// ---------------------------------------------------------------------------
__device__ __forceinline__ uint32_t f2tf(float f) {
    uint32_t u;
    asm("cvt.rna.tf32.f32 %0, %1;" : "=r"(u) : "f"(f));
    return u;
}

__device__ __forceinline__ void mma8(float& d0, float& d1, float& d2, float& d3,
                                     uint32_t a0, uint32_t a1, uint32_t a2, uint32_t a3,
                                     uint32_t b0, uint32_t b1) {
    asm volatile(
        "mma.sync.aligned.m16n8k8.row.col.f32.tf32.tf32.f32 "
        "{%0,%1,%2,%3}, {%4,%5,%6,%7}, {%8,%9}, {%0,%1,%2,%3};"
        : "+f"(d0), "+f"(d1), "+f"(d2), "+f"(d3)
        : "r"(a0), "r"(a1), "r"(a2), "r"(a3), "r"(b0), "r"(b1));
}

// ---------------------------------------------------------------------------
// Tiled tf32 MMA GEMM: C[m0:m0+128, n0:n0+64] = A @ B + bias
// A row-major MxK (lda), B row-major KxN (ldb), C row-major (ldc).
// Block = 256 threads (8 warps, 4x2 warp grid; warp tile 32x32).
// ---------------------------------------------------------------------------
#define LDA_S 36   // 32 + 4 pad
#define LDB_S 72   // 64 + 8 pad

__device__ __forceinline__ void gemm_mma_tile(
    const float* __restrict__ A, int lda,
    const float* __restrict__ Bm, int ldb,
    const float* __restrict__ bias,
    float* __restrict__ C, int ldc,
    int K, int m0, int n0)
{
    __shared__ uint32_t As[128 * LDA_S];   // [m][k] tf32
    __shared__ uint32_t Bs[32 * LDB_S];    // [k][n] tf32

    const int tid  = threadIdx.x;
    const int warp = tid >> 5;
    const int lane = tid & 31;
    const int g    = lane >> 2;   // 0..7
    const int tig  = lane & 3;    // 0..3

    const int wm = (warp >> 1) * 32;  // warp row offset in tile (0..96)
    const int wn = (warp & 1) * 32;   // warp col offset in tile (0 or 32)

    // staging indices
    const int ar = tid >> 1;          // 0..127
    const int ac = (tid & 1) * 16;    // 0 or 16
    const int br = tid >> 3;          // 0..31
    const int bc = (tid & 7) * 8;     // 0..56

    float acc[2][4][4];
#pragma unroll
    for (int i = 0; i < 2; i++)
#pragma unroll
        for (int j = 0; j < 4; j++)
#pragma unroll
            for (int l = 0; l < 4; l++) acc[i][j][l] = 0.f;

    for (int k0 = 0; k0 < K; k0 += 32) {
#pragma unroll
        for (int i = 0; i < 4; i++) {
            float4 v = *(const float4*)(A + (size_t)(m0 + ar) * lda + k0 + ac + i * 4);
            uint4 t;
            t.x = f2tf(v.x); t.y = f2tf(v.y); t.z = f2tf(v.z); t.w = f2tf(v.w);
            *(uint4*)(As + ar * LDA_S + ac + i * 4) = t;
        }
#pragma unroll
        for (int i = 0; i < 2; i++) {
            float4 v = *(const float4*)(Bm + (size_t)(k0 + br) * ldb + n0 + bc + i * 4);
            uint4 t;
            t.x = f2tf(v.x); t.y = f2tf(v.y); t.z = f2tf(v.z); t.w = f2tf(v.w);
            *(uint4*)(Bs + br * LDB_S + bc + i * 4) = t;
        }
        __syncthreads();

#pragma unroll
        for (int kk = 0; kk < 32; kk += 8) {
            uint32_t af[2][4];
#pragma unroll
            for (int ms = 0; ms < 2; ms++) {
                const int mb = wm + ms * 16;
                af[ms][0] = As[(mb + g) * LDA_S + kk + tig];
                af[ms][1] = As[(mb + g + 8) * LDA_S + kk + tig];
                af[ms][2] = As[(mb + g) * LDA_S + kk + tig + 4];
                af[ms][3] = As[(mb + g + 8) * LDA_S + kk + tig + 4];
            }
#pragma unroll
            for (int ns = 0; ns < 4; ns++) {
                uint32_t b0 = Bs[(kk + tig) * LDB_S + wn + ns * 8 + g];
                uint32_t b1 = Bs[(kk + tig + 4) * LDB_S + wn + ns * 8 + g];
                mma8(acc[0][ns][0], acc[0][ns][1], acc[0][ns][2], acc[0][ns][3],
                     af[0][0], af[0][1], af[0][2], af[0][3], b0, b1);
                mma8(acc[1][ns][0], acc[1][ns][1], acc[1][ns][2], acc[1][ns][3],
                     af[1][0], af[1][1], af[1][2], af[1][3], b0, b1);
            }
        }
        __syncthreads();
    }

    // epilogue: C rows (g, g+8), cols 2*tig, 2*tig+1 per n-subtile
#pragma unroll
    for (int ms = 0; ms < 2; ms++) {
#pragma unroll
        for (int ns = 0; ns < 4; ns++) {
            const int r0 = m0 + wm + ms * 16 + g;
            const int c  = n0 + wn + ns * 8 + 2 * tig;
            const float bx = __ldg(&bias[c]);
            const float by = __ldg(&bias[c + 1]);
            float2 v0 = make_float2(acc[ms][ns][0] + bx, acc[ms][ns][1] + by);
            float2 v1 = make_float2(acc[ms][ns][2] + bx, acc[ms][ns][3] + by);
            *(float2*)(C + (size_t)r0 * ldc + c)       = v0;
            *(float2*)(C + (size_t)(r0 + 8) * ldc + c) = v1;
        }
    }
}

// ---------------------------------------------------------------------------
// QKV projection: grid (S/128, B*H, 3), block 256
// ---------------------------------------------------------------------------
__global__ __launch_bounds__(256) void qkv_kernel(
    const float* __restrict__ x,
    const float* __restrict__ wq, const float* __restrict__ bq,
    const float* __restrict__ wk, const float* __restrict__ bk,
    const float* __restrict__ wv, const float* __restrict__ bv)
{
    const int which = blockIdx.z;
    const int bh = blockIdx.y;
    const int b = bh >> 4;
    const int h = bh & (H_ - 1);

    const float* W; const float* bias; float* C;
    if (which == 0)      { W = wq; bias = bq; C = g_q; }
    else if (which == 1) { W = wk; bias = bk; C = g_k; }
    else                 { W = wv; bias = bv; C = g_v; }

    gemm_mma_tile(x + (size_t)b * S_ * E_, E_,
                  W + (size_t)h * E_ * DH_, DH_,
                  bias + (size_t)h * DH_,
                  C + (size_t)bh * S_ * DH_, DH_,
                  E_, blockIdx.x * 128, 0);
}

// ---------------------------------------------------------------------------
// Output projection: grid (B*S/128, E/64), block 256
// ---------------------------------------------------------------------------
__global__ __launch_bounds__(256) void proj_kernel(
    const float* __restrict__ wo, const float* __restrict__ bo,
    float* __restrict__ out)
{
    gemm_mma_tile(g_ao, E_, wo, E_, bo, out, E_, E_,
                  blockIdx.x * 128, blockIdx.y * 64);
}

// ---------------------------------------------------------------------------
// Flash attention with tf32 MMA.
// Block 256 (8 warps); each warp owns 16 query rows -> 128 q rows / CTA.
// Key tiles of 64. grid (S/128, B*H).
// SMEM (dynamic): Ks[64][68], Vs[64][72], Ps[8][16][68], mk[64]
// ---------------------------------------------------------------------------
#define LDK 68
#define LDV 72
#define LDP 68
#define KS_SZ (64 * LDK)
#define VS_SZ (64 * LDV)
#define PS_SZ (8 * 16 * LDP)
#define ATTN_SMEM_BYTES ((KS_SZ + VS_SZ + PS_SZ + 64) * 4)

__global__ __launch_bounds__(256) void attn_kernel(const int* __restrict__ mask)
{
    extern __shared__ uint32_t dsm[];
    uint32_t* Ks = dsm;
    uint32_t* Vs = Ks + KS_SZ;
    uint32_t* Ps = Vs + VS_SZ;
    float*    mk = (float*)(Ps + PS_SZ);

    const int tid  = threadIdx.x;
    const int warp = tid >> 5;
    const int lane = tid & 31;
    const int g    = lane >> 2;
    const int tig  = lane & 3;

    const int bh = blockIdx.y;
    const int b  = bh >> 4;
    const int h  = bh & (H_ - 1);
    const int qbase = blockIdx.x * 128 + warp * 16;

    // exp2-domain scale: (1/sqrt(64)) * log2(e)
    const float SC = 0.18033688011112158f;

    // persistent Q A-fragments (16 rows x 64 cols, 8 k-steps)
    const float* qp = g_q + ((size_t)bh * S_ + qbase) * DH_;
    uint32_t qf[8][4];
#pragma unroll
    for (int ks = 0; ks < 8; ks++) {
        const int c0 = ks * 8 + tig;
        qf[ks][0] = f2tf(qp[(size_t)g * DH_ + c0]);
        qf[ks][1] = f2tf(qp[(size_t)(g + 8) * DH_ + c0]);
        qf[ks][2] = f2tf(qp[(size_t)g * DH_ + c0 + 4]);
        qf[ks][3] = f2tf(qp[(size_t)(g + 8) * DH_ + c0 + 4]);
    }

    float oacc[8][4];
#pragma unroll
    for (int i = 0; i < 8; i++)
#pragma unroll
        for (int j = 0; j < 4; j++) oacc[i][j] = 0.f;
    float rm0 = -1e30f, rm1 = -1e30f;   // running max (exp2 domain), rows g / g+8
    float rl0 = 0.f,    rl1 = 0.f;      // per-thread partial row sums

    const float* kb = g_k + (size_t)bh * S_ * DH_;
    const float* vb = g_v + (size_t)bh * S_ * DH_;
    const int lr = tid >> 2;          // staging row 0..63
    const int lc = (tid & 3) * 16;    // staging col base

    uint32_t* Pw = Ps + warp * 16 * LDP;

    for (int kt = 0; kt < S_; kt += 64) {
        // stage K, V tiles (tf32) + mask
#pragma unroll
        for (int i = 0; i < 4; i++) {
            float4 kv = *(const float4*)(kb + (size_t)(kt + lr) * DH_ + lc + i * 4);
            uint4 t;
            t.x = f2tf(kv.x); t.y = f2tf(kv.y); t.z = f2tf(kv.z); t.w = f2tf(kv.w);
            *(uint4*)(Ks + lr * LDK + lc + i * 4) = t;
            float4 vv = *(const float4*)(vb + (size_t)(kt + lr) * DH_ + lc + i * 4);
            uint4 u;
            u.x = f2tf(vv.x); u.y = f2tf(vv.y); u.z = f2tf(vv.z); u.w = f2tf(vv.w);
            *(uint4*)(Vs + lr * LDV + lc + i * 4) = u;
        }
        if (tid < 64)
            mk[tid] = (mask[b * S_ + kt + tid] == 0) ? -1e9f : 0.f;
        __syncthreads();

        // ---- scores = Q @ K^T  (C-frag: rows g/g+8, cols 2tig/2tig+1 per n-tile)
        float sacc[8][4];
#pragma unroll
        for (int i = 0; i < 8; i++)
#pragma unroll
            for (int j = 0; j < 4; j++) sacc[i][j] = 0.f;
#pragma unroll
        for (int ks = 0; ks < 8; ks++) {
#pragma unroll
            for (int nt = 0; nt < 8; nt++) {
                uint32_t b0 = Ks[(nt * 8 + g) * LDK + ks * 8 + tig];
                uint32_t b1 = Ks[(nt * 8 + g) * LDK + ks * 8 + tig + 4];
                mma8(sacc[nt][0], sacc[nt][1], sacc[nt][2], sacc[nt][3],
                     qf[ks][0], qf[ks][1], qf[ks][2], qf[ks][3], b0, b1);
            }
        }

        // ---- scale + mask (exp2 domain), tile row-max
        float tm0 = -1e30f, tm1 = -1e30f;
#pragma unroll
        for (int nt = 0; nt < 8; nt++) {
            const float m0v = mk[nt * 8 + 2 * tig];
            const float m1v = mk[nt * 8 + 2 * tig + 1];
            sacc[nt][0] = sacc[nt][0] * SC + m0v;
            sacc[nt][1] = sacc[nt][1] * SC + m1v;
            sacc[nt][2] = sacc[nt][2] * SC + m0v;
            sacc[nt][3] = sacc[nt][3] * SC + m1v;
            tm0 = fmaxf(tm0, fmaxf(sacc[nt][0], sacc[nt][1]));
            tm1 = fmaxf(tm1, fmaxf(sacc[nt][2], sacc[nt][3]));
        }
        tm0 = fmaxf(tm0, __shfl_xor_sync(0xffffffff, tm0, 1));
        tm0 = fmaxf(tm0, __shfl_xor_sync(0xffffffff, tm0, 2));
        tm1 = fmaxf(tm1, __shfl_xor_sync(0xffffffff, tm1, 1));
        tm1 = fmaxf(tm1, __shfl_xor_sync(0xffffffff, tm1, 2));

        const float nm0 = fmaxf(rm0, tm0);
        const float nm1 = fmaxf(rm1, tm1);
        const float c0 = exp2f(rm0 - nm0);
        const float c1 = exp2f(rm1 - nm1);
        rm0 = nm0; rm1 = nm1;
        rl0 *= c0;  rl1 *= c1;
#pragma unroll
        for (int nt = 0; nt < 8; nt++) {
            oacc[nt][0] *= c0; oacc[nt][1] *= c0;
            oacc[nt][2] *= c1; oacc[nt][3] *= c1;
        }

        // ---- P = exp2(s - m); accumulate partial row-sums; stage to SMEM
#pragma unroll
        for (int nt = 0; nt < 8; nt++) {
            const float p0 = exp2f(sacc[nt][0] - nm0);
            const float p1 = exp2f(sacc[nt][1] - nm0);
            const float p2 = exp2f(sacc[nt][2] - nm1);
            const float p3 = exp2f(sacc[nt][3] - nm1);
            rl0 += p0 + p1;
            rl1 += p2 + p3;
            const int col = nt * 8 + 2 * tig;
            Pw[g * LDP + col]           = f2tf(p0);
            Pw[g * LDP + col + 1]       = f2tf(p1);
            Pw[(g + 8) * LDP + col]     = f2tf(p2);
            Pw[(g + 8) * LDP + col + 1] = f2tf(p3);
        }
        __syncwarp();

        // ---- O += P @ V
#pragma unroll
        for (int ks = 0; ks < 8; ks++) {
            uint32_t a0 = Pw[g * LDP + ks * 8 + tig];
            uint32_t a1 = Pw[(g + 8) * LDP + ks * 8 + tig];
            uint32_t a2 = Pw[g * LDP + ks * 8 + tig + 4];
            uint32_t a3 = Pw[(g + 8) * LDP + ks * 8 + tig + 4];
#pragma unroll
            for (int nt = 0; nt < 8; nt++) {
                uint32_t b0 = Vs[(ks * 8 + tig) * LDV + nt * 8 + g];
                uint32_t b1 = Vs[(ks * 8 + tig + 4) * LDV + nt * 8 + g];
                mma8(oacc[nt][0], oacc[nt][1], oacc[nt][2], oacc[nt][3],
                     a0, a1, a2, a3, b0, b1);
            }
        }
        __syncthreads();
    }

    // final row sums across the 4 lanes of each row group
    rl0 += __shfl_xor_sync(0xffffffff, rl0, 1);
    rl0 += __shfl_xor_sync(0xffffffff, rl0, 2);
    rl1 += __shfl_xor_sync(0xffffffff, rl1, 1);
    rl1 += __shfl_xor_sync(0xffffffff, rl1, 2);
    const float inv0 = 1.f / rl0;
    const float inv1 = 1.f / rl1;

    float* ob = g_ao + ((size_t)b * S_ + qbase) * E_ + (size_t)h * DH_;
#pragma unroll
    for (int nt = 0; nt < 8; nt++) {
        const int col = nt * 8 + 2 * tig;
        float2 v0 = make_float2(oacc[nt][0] * inv0, oacc[nt][1] * inv0);
        float2 v1 = make_float2(oacc[nt][2] * inv1, oacc[nt][3] * inv1);
        *(float2*)(ob + (size_t)g * E_ + col)       = v0;
        *(float2*)(ob + (size_t)(g + 8) * E_ + col) = v1;
    }
}

// ---------------------------------------------------------------------------
extern "C" void kernel_launch(void* const* d_in, const int* in_sizes, int n_in,
                              void* d_out, int out_size)
{
    const float* x    = (const float*)d_in[0];
    const int*   mask = (const int*)  d_in[1];
    const float* wq   = (const float*)d_in[2];
    const float* bq   = (const float*)d_in[3];
    const float* wk   = (const float*)d_in[4];
    const float* bk   = (const float*)d_in[5];
    const float* wv   = (const float*)d_in[6];
    const float* bv   = (const float*)d_in[7];
    const float* wo   = (const float*)d_in[8];
    const float* bo   = (const float*)d_in[9];
    float* out = (float*)d_out;

    cudaFuncSetAttribute(attn_kernel,
                         cudaFuncAttributeMaxDynamicSharedMemorySize,
                         ATTN_SMEM_BYTES);

    dim3 g1(S_ / 128, B_ * H_, 3);
    qkv_kernel<<<g1, 256>>>(x, wq, bq, wk, bk, wv, bv);

    dim3 g2(S_ / 128, B_ * H_);
    attn_kernel<<<g2, 256, ATTN_SMEM_BYTES>>>(mask);

    dim3 g3((B_ * S_) / 128, E_ / 64);
    proj_kernel<<<g3, 256>>>(wo, bo, out);
}